// round 2
// baseline (speedup 1.0000x reference)
#include <cuda_runtime.h>
#include <math.h>

#define BB   16
#define HH   256
#define LL   4096
#define DIN  100
#define DMID 512
#define DOUTP 100
#define NST  32     // complex states per head
#define CH   64     // chunk length
#define NC   64     // number of chunks (CH*NC = LL)

// ---------------- device scratch (allocation-free rule) ----------------
__device__ float g_u[BB * HH * LL];       // encoder output, (B,H,L)
__device__ float g_E[BB * HH * LL];       // chunk states -> prev states (scan in place)
__device__ float g_hres[BB * HH * LL];    // post-gelu residual, (B,H,L)
__device__ float g_tln[BB * LL * HH];     // layernorm output, (B,L,H)
__device__ float g_z[BB * LL * DMID];     // MLP hidden
__device__ float g_V[HH * CH * CH];       // [h][t][s]  : state matrix (s = 2n / 2n+1 re/im)
__device__ float g_CM[HH * 128 * CH];     // [h][k][t]  : [Toeplitz(k) | G] combined, k-major
__device__ float g_wS[HH * NST * 2];      // w^64 per (h,n), re/im

__device__ __forceinline__ float gelu_f(float x) {
    return 0.5f * x * (1.0f + erff(x * 0.70710678118654752f));
}

// ---------------- precompute per-head matrices ----------------
// block = head h (256 blocks), 64 threads (t = within-chunk index)
__global__ void precompute_kernel(const float* __restrict__ log_dt,
                                  const float* __restrict__ log_A_real,
                                  const float* __restrict__ A_imag,
                                  const float* __restrict__ B_re,
                                  const float* __restrict__ B_im,
                                  const float* __restrict__ C_re,
                                  const float* __restrict__ C_im)
{
    int h = blockIdx.x;
    int t = threadIdx.x;   // 0..63
    __shared__ float s_dtr[NST], s_dti[NST], s_c2r[NST], s_c2i[NST];
    __shared__ float s_k[CH];

    float dt = expf(log_dt[h]);
    if (t < NST) {
        int n = t;
        float Ar = -expf(log_A_real[h * NST + n]);
        float Ai = A_imag[h * NST + n];
        float dtr = dt * Ar, dti = dt * Ai;
        // exp(dtA) - 1
        float er = expf(dtr);
        float Er = er * cosf(dti) - 1.0f;
        float Ei = er * sinf(dti);
        // B*C
        float br = B_re[h * NST + n], bi = B_im[h * NST + n];
        float cr = C_re[h * NST + n], ci = C_im[h * NST + n];
        float BCr = br * cr - bi * ci;
        float BCi = br * ci + bi * cr;
        // C' = BC * (exp(dtA)-1) / A   ; C2 = 2*C'
        float numr = BCr * Er - BCi * Ei;
        float numi = BCr * Ei + BCi * Er;
        float den = Ar * Ar + Ai * Ai;
        float cpr = (numr * Ar + numi * Ai) / den;
        float cpi = (numi * Ar - numr * Ai) / den;
        s_c2r[n] = 2.0f * cpr;
        s_c2i[n] = 2.0f * cpi;
        s_dtr[n] = dtr;
        s_dti[n] = dti;
        // w^64
        float e64 = expf(64.0f * dtr);
        g_wS[(h * NST + n) * 2 + 0] = e64 * cosf(64.0f * dti);
        g_wS[(h * NST + n) * 2 + 1] = e64 * sinf(64.0f * dti);
    }
    __syncthreads();

    float kt = 0.0f;
    for (int n = 0; n < NST; n++) {
        float dtr = s_dtr[n], dti = s_dti[n];
        float c2r = s_c2r[n], c2i = s_c2i[n];
        // V[h][t][2n,2n+1] = w^{63-t}
        float p = (float)(63 - t);
        float ep = expf(p * dtr);
        g_V[((long)h * CH + t) * CH + 2 * n]     = ep * cosf(p * dti);
        g_V[((long)h * CH + t) * CH + 2 * n + 1] = ep * sinf(p * dti);
        // k[t] = sum_n Re(C2 * w^t)
        float pt = (float)t;
        float et = expf(pt * dtr);
        float wr = et * cosf(pt * dti), wi = et * sinf(pt * dti);
        kt += c2r * wr - c2i * wi;
        // G: coefficients of P_re/P_im: 2Re(C w^{t+1} P) = Re(C2 w^{t+1})*Pre - Im(C2 w^{t+1})*Pim
        float p1 = (float)(t + 1);
        float e1 = expf(p1 * dtr);
        float w1r = e1 * cosf(p1 * dti), w1i = e1 * sinf(p1 * dti);
        g_CM[((long)h * 128 + 64 + 2 * n) * CH + t]     = c2r * w1r - c2i * w1i;
        g_CM[((long)h * 128 + 64 + 2 * n + 1) * CH + t] = -(c2r * w1i + c2i * w1r);
    }
    s_k[t] = kt;
    __syncthreads();
    // Toeplitz rows: CM[j][t] = k[t-j] for j<=t else 0
    for (int j = 0; j < CH; j++) {
        g_CM[((long)h * 128 + j) * CH + t] = (j <= t) ? s_k[t - j] : 0.0f;
    }
}

// ---------------- generic SGEMM: C[M,N] = A[M,K] * B[N,K]^T + bias (+gelu) ----------------
// 128x64 tile, BK=16, 256 threads, 8x4 per-thread microtile. M % 128 == 0, K % 4 == 0.
template <bool GELU, bool BIAS_M>
__global__ void __launch_bounds__(256, 2)
sgemm_abT(const float* __restrict__ A, const float* __restrict__ Bm,
          const float* __restrict__ bias, float* __restrict__ C,
          int M, int N, int K, int lda, int ldb, int ldc,
          long azs, long bzs, long czs)
{
    const float* Ab = A + (long)blockIdx.z * azs;
    const float* Bb = Bm + (long)blockIdx.z * bzs;
    float* Cb = C + (long)blockIdx.z * czs;

    __shared__ float As[16][132];
    __shared__ float Bs[16][68];

    int tid = threadIdx.x;
    int tx = tid & 15, ty = tid >> 4;
    int m0 = blockIdx.y * 128, n0 = blockIdx.x * 64;

    float acc[8][4];
#pragma unroll
    for (int i = 0; i < 8; i++)
#pragma unroll
        for (int j = 0; j < 4; j++) acc[i][j] = 0.0f;

    for (int k0 = 0; k0 < K; k0 += 16) {
#pragma unroll
        for (int r = 0; r < 2; r++) {
            int i = tid + 256 * r;
            int am = i >> 2, ak = (i & 3) << 2;
            float4 v = make_float4(0.f, 0.f, 0.f, 0.f);
            if (k0 + ak < K)
                v = *(const float4*)(Ab + (long)(m0 + am) * lda + k0 + ak);
            As[ak][am] = v.x; As[ak + 1][am] = v.y;
            As[ak + 2][am] = v.z; As[ak + 3][am] = v.w;
        }
        {
            int bn = tid >> 2, bk = (tid & 3) << 2;
            float4 v = make_float4(0.f, 0.f, 0.f, 0.f);
            if ((k0 + bk < K) && (n0 + bn < N))
                v = *(const float4*)(Bb + (long)(n0 + bn) * ldb + k0 + bk);
            Bs[bk][bn] = v.x; Bs[bk + 1][bn] = v.y;
            Bs[bk + 2][bn] = v.z; Bs[bk + 3][bn] = v.w;
        }
        __syncthreads();
#pragma unroll
        for (int kk = 0; kk < 16; kk++) {
            float4 a0 = *(const float4*)&As[kk][ty * 8];
            float4 a1 = *(const float4*)&As[kk][ty * 8 + 4];
            float4 b0 = *(const float4*)&Bs[kk][tx * 4];
            float a[8] = {a0.x, a0.y, a0.z, a0.w, a1.x, a1.y, a1.z, a1.w};
            float b[4] = {b0.x, b0.y, b0.z, b0.w};
#pragma unroll
            for (int i = 0; i < 8; i++)
#pragma unroll
                for (int j = 0; j < 4; j++)
                    acc[i][j] = fmaf(a[i], b[j], acc[i][j]);
        }
        __syncthreads();
    }

#pragma unroll
    for (int i = 0; i < 8; i++) {
        int m = m0 + ty * 8 + i;
        float bm = BIAS_M ? bias[m] : 0.0f;
#pragma unroll
        for (int j = 0; j < 4; j++) {
            int n = n0 + tx * 4 + j;
            if (n < N) {
                float v = acc[i][j] + (BIAS_M ? bm : bias[n]);
                if (GELU) v = gelu_f(v);
                Cb[(long)m * ldc + n] = v;
            }
        }
    }
}

// ---------------- stage A: chunk-local end states  E[c][s] = sum_t U[c][t]*V[t][s] ----------------
// block per (b,h) = 4096 blocks, 256 threads, 4x4 microtile over (c,s)
__global__ void __launch_bounds__(256, 2) stageA_kernel()
{
    int bh = blockIdx.x;
    int h = bh & (HH - 1);
    __shared__ float U[CH][68];
    __shared__ float Vt[CH][68];
    int tid = threadIdx.x;
    int tx = tid & 15, ty = tid >> 4;
    const float* up = g_u + (long)bh * LL;
    const float* vp = g_V + (long)h * CH * CH;
#pragma unroll
    for (int r = 0; r < 4; r++) {
        int i = tid + 256 * r;
        int c = i >> 4, t4 = (i & 15) << 2;
        *(float4*)&U[c][t4] = *(const float4*)(up + c * 64 + t4);
        *(float4*)&Vt[c][t4] = *(const float4*)(vp + c * 64 + t4);
    }
    __syncthreads();

    float acc[4][4];
#pragma unroll
    for (int i = 0; i < 4; i++)
#pragma unroll
        for (int j = 0; j < 4; j++) acc[i][j] = 0.0f;

#pragma unroll 8
    for (int t = 0; t < 64; t++) {
        float a[4];
#pragma unroll
        for (int i = 0; i < 4; i++) a[i] = U[ty * 4 + i][t];
        float4 b4 = *(const float4*)&Vt[t][tx * 4];
        float b[4] = {b4.x, b4.y, b4.z, b4.w};
#pragma unroll
        for (int i = 0; i < 4; i++)
#pragma unroll
            for (int j = 0; j < 4; j++)
                acc[i][j] = fmaf(a[i], b[j], acc[i][j]);
    }

    float* ep = g_E + (long)bh * LL;
#pragma unroll
    for (int i = 0; i < 4; i++) {
        float4 v = make_float4(acc[i][0], acc[i][1], acc[i][2], acc[i][3]);
        *(float4*)(ep + (ty * 4 + i) * 64 + tx * 4) = v;
    }
}

// ---------------- stage B: cross-chunk scan (in place: E[c] -> P[c] = state entering chunk c) ----
__global__ void scan_kernel()
{
    int gid = blockIdx.x * blockDim.x + threadIdx.x;   // 131072 threads
    int bh = gid >> 5;
    int n = gid & 31;
    int h = bh & (HH - 1);
    float2* E2 = (float2*)g_E + (long)bh * (LL / 2);
    float wr = g_wS[(h * NST + n) * 2 + 0];
    float wi = g_wS[(h * NST + n) * 2 + 1];
    float sr = 0.0f, si = 0.0f;
    for (int c = 0; c < NC; c++) {
        float2 e = E2[c * 32 + n];
        E2[c * 32 + n] = make_float2(sr, si);
        float nsr = wr * sr - wi * si + e.x;
        si = wr * si + wi * sr + e.y;
        sr = nsr;
    }
}

// ---------------- stage C: Y = [u_chunk | P] * CM^T, + Dskip*u, gelu, +u -> hres ----------------
__global__ void __launch_bounds__(256, 1) stageC_kernel(const float* __restrict__ Dskip)
{
    int bh = blockIdx.x;
    int h = bh & (HH - 1);
    __shared__ float In[CH][132];     // [c][k], k<64: u, k>=64: P
    __shared__ float CMs[16][68];
    int tid = threadIdx.x;
    int tx = tid & 15, ty = tid >> 4;
    const float* up = g_u + (long)bh * LL;
    const float* pp = g_E + (long)bh * LL;
#pragma unroll
    for (int r = 0; r < 4; r++) {
        int i = tid + 256 * r;
        int c = i >> 4, k4 = (i & 15) << 2;
        *(float4*)&In[c][k4] = *(const float4*)(up + c * 64 + k4);
        *(float4*)&In[c][64 + k4] = *(const float4*)(pp + c * 64 + k4);
    }

    float acc[4][4];
#pragma unroll
    for (int i = 0; i < 4; i++)
#pragma unroll
        for (int j = 0; j < 4; j++) acc[i][j] = 0.0f;

    const float* cmp = g_CM + (long)h * 128 * CH;
    for (int k0 = 0; k0 < 128; k0 += 16) {
        __syncthreads();
        {
            int kk = tid >> 4, t4 = (tid & 15) << 2;
            *(float4*)&CMs[kk][t4] = *(const float4*)(cmp + (k0 + kk) * 64 + t4);
        }
        __syncthreads();
#pragma unroll
        for (int kk = 0; kk < 16; kk++) {
            float a[4];
#pragma unroll
            for (int i = 0; i < 4; i++) a[i] = In[ty * 4 + i][k0 + kk];
            float4 b4 = *(const float4*)&CMs[kk][tx * 4];
            float b[4] = {b4.x, b4.y, b4.z, b4.w};
#pragma unroll
            for (int i = 0; i < 4; i++)
#pragma unroll
                for (int j = 0; j < 4; j++)
                    acc[i][j] = fmaf(a[i], b[j], acc[i][j]);
        }
    }

    float dsk = Dskip[h];
    float* hp = g_hres + (long)bh * LL;
#pragma unroll
    for (int i = 0; i < 4; i++) {
        int c = ty * 4 + i;
        float vv[4];
#pragma unroll
        for (int j = 0; j < 4; j++) {
            int t = tx * 4 + j;
            float uval = In[c][t];
            float y = acc[i][j] + dsk * uval;
            y = gelu_f(y);
            vv[j] = y + uval;
        }
        float4 o = make_float4(vv[0], vv[1], vv[2], vv[3]);
        *(float4*)(hp + c * 64 + tx * 4) = o;
    }
}

// ---------------- layernorm + transpose (B,H,L) -> (B,L,H) ----------------
// grid (L/32, B), 256 threads; tile 256H x 32L
__global__ void __launch_bounds__(256, 1) layernorm_kernel(const float* __restrict__ ln_g,
                                                           const float* __restrict__ ln_b)
{
    int b = blockIdx.y;
    int l0 = blockIdx.x * 32;
    __shared__ float tile[256][33];
    int tid = threadIdx.x;
    int w = tid >> 5, lane = tid & 31;
    const float* hp = g_hres + (long)b * HH * LL;
    for (int hh = w; hh < 256; hh += 8) {
        tile[hh][lane] = hp[(long)hh * LL + l0 + lane];
    }
    __syncthreads();
    float* op = g_tln + ((long)b * LL + l0) * HH;
#pragma unroll
    for (int q = 0; q < 4; q++) {
        int tok = w * 4 + q;
        float s = 0.0f, sq = 0.0f;
#pragma unroll
        for (int j = 0; j < 8; j++) {
            float v = tile[lane + 32 * j][tok];
            s += v;
            sq += v * v;
        }
#pragma unroll
        for (int o = 16; o > 0; o >>= 1) {
            s += __shfl_xor_sync(0xffffffffu, s, o);
            sq += __shfl_xor_sync(0xffffffffu, sq, o);
        }
        float mean = s * (1.0f / 256.0f);
        float var = sq * (1.0f / 256.0f) - mean * mean;
        float rstd = rsqrtf(var + 1e-5f);
#pragma unroll
        for (int j = 0; j < 8; j++) {
            int hh = lane + 32 * j;
            float v = (tile[hh][tok] - mean) * rstd * ln_g[hh] + ln_b[hh];
            op[(long)tok * HH + hh] = v;
        }
    }
}

// ---------------- launcher ----------------
extern "C" void kernel_launch(void* const* d_in, const int* in_sizes, int n_in,
                              void* d_out, int out_size)
{
    const float* x          = (const float*)d_in[0];
    const float* enc_w      = (const float*)d_in[1];
    const float* enc_b      = (const float*)d_in[2];
    const float* log_dt     = (const float*)d_in[3];
    const float* log_A_real = (const float*)d_in[4];
    const float* A_imag     = (const float*)d_in[5];
    const float* B_re       = (const float*)d_in[6];
    const float* B_im       = (const float*)d_in[7];
    const float* C_re       = (const float*)d_in[8];
    const float* C_im       = (const float*)d_in[9];
    const float* Dskip      = (const float*)d_in[10];
    const float* ln_g       = (const float*)d_in[11];
    const float* ln_b       = (const float*)d_in[12];
    const float* dec1_w     = (const float*)d_in[13];
    const float* dec1_b     = (const float*)d_in[14];
    const float* dec2_w     = (const float*)d_in[15];
    const float* dec2_b     = (const float*)d_in[16];
    float* out = (float*)d_out;

    void *pu = 0, *ptln = 0, *pz = 0;
    cudaGetSymbolAddress(&pu, g_u);
    cudaGetSymbolAddress(&ptln, g_tln);
    cudaGetSymbolAddress(&pz, g_z);

    // 1. per-head S4 matrices
    precompute_kernel<<<HH, 64>>>(log_dt, log_A_real, A_imag, B_re, B_im, C_re, C_im);

    // 2. encoder: per b, u_b(256 x 4096) = enc_w(256x100) * x_b(4096x100)^T, bias on M(=h)
    sgemm_abT<false, true><<<dim3(LL / 64, HH / 128, BB), 256>>>(
        enc_w, x, enc_b, (float*)pu,
        HH, LL, DIN, DIN, DIN, LL,
        0L, (long)LL * DIN, (long)HH * LL);

    // 3. chunk states
    stageA_kernel<<<BB * HH, 256>>>();

    // 4. cross-chunk scan
    scan_kernel<<<(BB * HH * NST) / 256, 256>>>();

    // 5. output stage + Dskip + gelu + residual
    stageC_kernel<<<BB * HH, 256>>>(Dskip);

    // 6. layernorm + transpose
    layernorm_kernel<<<dim3(LL / 32, BB), 256>>>(ln_g, ln_b);

    // 7. decoder MLP
    sgemm_abT<true, false><<<dim3(DMID / 64, (BB * LL) / 128, 1), 256>>>(
        (const float*)ptln, dec1_w, dec1_b, (float*)pz,
        BB * LL, DMID, HH, HH, HH, DMID, 0L, 0L, 0L);

    sgemm_abT<false, false><<<dim3((DOUTP + 63) / 64, (BB * LL) / 128, 1), 256>>>(
        (const float*)pz, dec2_w, dec2_b, out,
        BB * LL, DOUTP, DMID, DMID, DMID, DOUTP, 0L, 0L, 0L);
}

// round 5
// speedup vs baseline: 2.2577x; 2.2577x over previous
#include <cuda_runtime.h>
#include <cuda_bf16.h>
#include <math.h>
#include <stdint.h>

#define BB   16
#define HH   256
#define LL   4096
#define DIN  100
#define DMID 512
#define DOUTP 100
#define NST  32     // complex states per head
#define CH   64     // chunk length
#define NC   64     // number of chunks

// ---------------- device scratch (allocation-free rule) ----------------
__device__ float g_u[BB * HH * LL];       // encoder output, (B,H,L)
__device__ float g_E[BB * HH * LL];       // chunk states -> prev states (scan in place)
__device__ float g_hres[BB * HH * LL];    // post-gelu residual, (B,H,L)
__device__ float g_tln[BB * LL * HH];     // layernorm output, (B,L,H)
__device__ float g_z[BB * LL * DMID];     // MLP hidden
__device__ float g_V[HH * CH * CH];       // [h][t][s]
__device__ float g_CM[HH * 128 * CH];     // [h][k][t]
__device__ float g_wS[HH * NST * 2];      // w^64 per (h,n)

__device__ __forceinline__ float gelu_f(float x) {
    return 0.5f * x * (1.0f + erff(x * 0.70710678118654752f));
}

__device__ __forceinline__ void bf16_split2(float x, float y, uint32_t& hi, uint32_t& lo) {
    __nv_bfloat16 hx = __float2bfloat16_rn(x);
    __nv_bfloat16 lx = __float2bfloat16_rn(x - __bfloat162float(hx));
    __nv_bfloat16 hy = __float2bfloat16_rn(y);
    __nv_bfloat16 ly = __float2bfloat16_rn(y - __bfloat162float(hy));
    hi = (uint32_t)*(uint16_t*)&hx | ((uint32_t)*(uint16_t*)&hy << 16);
    lo = (uint32_t)*(uint16_t*)&lx | ((uint32_t)*(uint16_t*)&ly << 16);
}

__device__ __forceinline__ void mma16816(float* c, const uint32_t* a, uint32_t b0, uint32_t b1) {
    asm volatile(
        "mma.sync.aligned.m16n8k16.row.col.f32.bf16.bf16.f32 "
        "{%0,%1,%2,%3}, {%4,%5,%6,%7}, {%8,%9}, {%0,%1,%2,%3};"
        : "+f"(c[0]), "+f"(c[1]), "+f"(c[2]), "+f"(c[3])
        : "r"(a[0]), "r"(a[1]), "r"(a[2]), "r"(a[3]), "r"(b0), "r"(b1));
}

// ============ tensor-core GEMM via mma.sync: C[M,N] = A[M,K]*B[N,K]^T + bias ============
// tile 128x128, BK=32, 256 threads. bf16 hi/lo split (3 MMAs -> fp32-grade accuracy).
// TRANSPOSED: store out as (B,H,L) with m=token(b,l), n=h  (encoder path)
#define SASTRIDE 36   // uint16 stride (72B)
template <bool GELU, bool TRANSPOSED, bool KGUARD, bool NGUARD>
__global__ void __launch_bounds__(256)
gemm_mma(const float* __restrict__ A, const float* __restrict__ Bm,
         const float* __restrict__ bias, float* __restrict__ C,
         int M, int N, int K, int lda, int ldb, int ldc)
{
    __shared__ __align__(16) char sm_raw[36864];
    uint16_t* sAh = (uint16_t*)sm_raw;                    // [128][36]
    uint16_t* sAl = (uint16_t*)(sm_raw + 9216);
    uint16_t* sBh = (uint16_t*)(sm_raw + 18432);
    uint16_t* sBl = (uint16_t*)(sm_raw + 27648);
    float* stage = (float*)sm_raw;

    int tid = threadIdx.x;
    int warp = tid >> 5, lane = tid & 31;
    int warp_m = warp >> 1, warp_n = warp & 1;
    int g = lane >> 2, tg = lane & 3;

    int m0 = blockIdx.y * 128, n0 = blockIdx.x * 128;
    int row = tid >> 1, half = tid & 1;
    const float* arow = A + (long)(m0 + row) * lda;
    const float* brow = Bm + (long)(n0 + row) * ldb;
    bool bvalid = !NGUARD || (n0 + row) < N;

    float acc[2][8][4];
#pragma unroll
    for (int mt = 0; mt < 2; mt++)
#pragma unroll
        for (int nt = 0; nt < 8; nt++)
#pragma unroll
            for (int q = 0; q < 4; q++) acc[mt][nt][q] = 0.0f;

    int nchunks = (K + 31) >> 5;
    for (int c = 0; c < nchunks; c++) {
        if (c) __syncthreads();
        int k0 = c << 5;
#pragma unroll
        for (int i = 0; i < 2; i++) {
            int kc = half * 16 + i * 8;   // 8 floats per iter
            int k = k0 + kc;
            float4 va0 = make_float4(0.f,0.f,0.f,0.f), va1 = va0, vb0 = va0, vb1 = va0;
            if (!KGUARD || k < K) {
                va0 = *(const float4*)(arow + k);
                if (!KGUARD || k + 4 < K) va1 = *(const float4*)(arow + k + 4);
                if (bvalid) {
                    vb0 = *(const float4*)(brow + k);
                    if (!KGUARD || k + 4 < K) vb1 = *(const float4*)(brow + k + 4);
                }
            }
            uint32_t h0,h1,h2,h3, l0,l1,l2,l3;
            bf16_split2(va0.x, va0.y, h0, l0);
            bf16_split2(va0.z, va0.w, h1, l1);
            bf16_split2(va1.x, va1.y, h2, l2);
            bf16_split2(va1.z, va1.w, h3, l3);
            *(uint2*)&sAh[row * SASTRIDE + kc]     = make_uint2(h0, h1);
            *(uint2*)&sAh[row * SASTRIDE + kc + 4] = make_uint2(h2, h3);
            *(uint2*)&sAl[row * SASTRIDE + kc]     = make_uint2(l0, l1);
            *(uint2*)&sAl[row * SASTRIDE + kc + 4] = make_uint2(l2, l3);
            bf16_split2(vb0.x, vb0.y, h0, l0);
            bf16_split2(vb0.z, vb0.w, h1, l1);
            bf16_split2(vb1.x, vb1.y, h2, l2);
            bf16_split2(vb1.z, vb1.w, h3, l3);
            *(uint2*)&sBh[row * SASTRIDE + kc]     = make_uint2(h0, h1);
            *(uint2*)&sBh[row * SASTRIDE + kc + 4] = make_uint2(h2, h3);
            *(uint2*)&sBl[row * SASTRIDE + kc]     = make_uint2(l0, l1);
            *(uint2*)&sBl[row * SASTRIDE + kc + 4] = make_uint2(l2, l3);
        }
        __syncthreads();

#pragma unroll
        for (int ks = 0; ks < 2; ks++) {
            int kb = ks * 16;
            uint32_t ah[2][4], al[2][4];
#pragma unroll
            for (int mt = 0; mt < 2; mt++) {
                int ra = warp_m * 32 + mt * 16;
                ah[mt][0] = *(uint32_t*)&sAh[(ra + g) * SASTRIDE + kb + tg * 2];
                ah[mt][1] = *(uint32_t*)&sAh[(ra + g + 8) * SASTRIDE + kb + tg * 2];
                ah[mt][2] = *(uint32_t*)&sAh[(ra + g) * SASTRIDE + kb + tg * 2 + 8];
                ah[mt][3] = *(uint32_t*)&sAh[(ra + g + 8) * SASTRIDE + kb + tg * 2 + 8];
                al[mt][0] = *(uint32_t*)&sAl[(ra + g) * SASTRIDE + kb + tg * 2];
                al[mt][1] = *(uint32_t*)&sAl[(ra + g + 8) * SASTRIDE + kb + tg * 2];
                al[mt][2] = *(uint32_t*)&sAl[(ra + g) * SASTRIDE + kb + tg * 2 + 8];
                al[mt][3] = *(uint32_t*)&sAl[(ra + g + 8) * SASTRIDE + kb + tg * 2 + 8];
            }
#pragma unroll
            for (int nt = 0; nt < 8; nt++) {
                int nb = warp_n * 64 + nt * 8 + g;
                uint32_t bh0 = *(uint32_t*)&sBh[nb * SASTRIDE + kb + tg * 2];
                uint32_t bh1 = *(uint32_t*)&sBh[nb * SASTRIDE + kb + tg * 2 + 8];
                uint32_t bl0 = *(uint32_t*)&sBl[nb * SASTRIDE + kb + tg * 2];
                uint32_t bl1 = *(uint32_t*)&sBl[nb * SASTRIDE + kb + tg * 2 + 8];
#pragma unroll
                for (int mt = 0; mt < 2; mt++) {
                    mma16816(acc[mt][nt], ah[mt], bh0, bh1);
                    mma16816(acc[mt][nt], ah[mt], bl0, bl1);
                    mma16816(acc[mt][nt], al[mt], bh0, bh1);
                }
            }
        }
    }
    __syncthreads();

    // -------- epilogue: staged through smem for coalesced stores --------
    for (int nh = 0; nh < 2; nh++) {
        if (warp_n == nh) {
#pragma unroll
            for (int mt = 0; mt < 2; mt++) {
#pragma unroll
                for (int nt = 0; nt < 8; nt++) {
                    int nl = nt * 8 + tg * 2;
                    int ng = n0 + nh * 64 + nl;
                    int r0 = warp_m * 32 + mt * 16 + g;
                    float b0v = (!NGUARD || ng < N) ? bias[ng] : 0.0f;
                    float b1v = (!NGUARD || ng + 1 < N) ? bias[ng + 1] : 0.0f;
                    float v0 = acc[mt][nt][0] + b0v;
                    float v1 = acc[mt][nt][1] + b1v;
                    float v2 = acc[mt][nt][2] + b0v;
                    float v3 = acc[mt][nt][3] + b1v;
                    if (GELU) { v0 = gelu_f(v0); v1 = gelu_f(v1); v2 = gelu_f(v2); v3 = gelu_f(v3); }
                    if (TRANSPOSED) {
                        stage[nl * 132 + r0]       = v0;
                        stage[(nl + 1) * 132 + r0] = v1;
                        stage[nl * 132 + r0 + 8]       = v2;
                        stage[(nl + 1) * 132 + r0 + 8] = v3;
                    } else {
                        stage[r0 * 68 + nl]           = v0;
                        stage[r0 * 68 + nl + 1]       = v1;
                        stage[(r0 + 8) * 68 + nl]     = v2;
                        stage[(r0 + 8) * 68 + nl + 1] = v3;
                    }
                }
            }
        }
        __syncthreads();
        if (TRANSPOSED) {
            int bidx = m0 >> 12;
            int l0 = m0 & 4095;
#pragma unroll
            for (int p = 0; p < 8; p++) {
                int nl = p * 8 + warp;
                int m4 = lane * 4;
                float4 v = *(float4*)&stage[nl * 132 + m4];
                int ng = n0 + nh * 64 + nl;
                *(float4*)&C[((long)((bidx << 8) + ng)) * 4096 + l0 + m4] = v;
            }
        } else {
#pragma unroll
            for (int p = 0; p < 8; p++) {
                int idx = tid + p * 256;
                int r = idx >> 4;
                int c4 = (idx & 15) * 4;
                int n = n0 + nh * 64 + c4;
                if (!NGUARD || n < N) {
                    float4 v = *(float4*)&stage[r * 68 + c4];
                    *(float4*)&C[(long)(m0 + r) * ldc + n] = v;
                }
            }
        }
        __syncthreads();
    }
}

// ---------------- precompute per-head matrices ----------------
__global__ void precompute_kernel(const float* __restrict__ log_dt,
                                  const float* __restrict__ log_A_real,
                                  const float* __restrict__ A_imag,
                                  const float* __restrict__ B_re,
                                  const float* __restrict__ B_im,
                                  const float* __restrict__ C_re,
                                  const float* __restrict__ C_im)
{
    int h = blockIdx.x;
    int t = threadIdx.x;   // 0..63
    __shared__ float s_dtr[NST], s_dti[NST], s_c2r[NST], s_c2i[NST];
    __shared__ float s_k[CH];

    float dt = expf(log_dt[h]);
    if (t < NST) {
        int n = t;
        float Ar = -expf(log_A_real[h * NST + n]);
        float Ai = A_imag[h * NST + n];
        float dtr = dt * Ar, dti = dt * Ai;
        float er = expf(dtr);
        float Er = er * cosf(dti) - 1.0f;
        float Ei = er * sinf(dti);
        float br = B_re[h * NST + n], bi = B_im[h * NST + n];
        float cr = C_re[h * NST + n], ci = C_im[h * NST + n];
        float BCr = br * cr - bi * ci;
        float BCi = br * ci + bi * cr;
        float numr = BCr * Er - BCi * Ei;
        float numi = BCr * Ei + BCi * Er;
        float den = Ar * Ar + Ai * Ai;
        float cpr = (numr * Ar + numi * Ai) / den;
        float cpi = (numi * Ar - numr * Ai) / den;
        s_c2r[n] = 2.0f * cpr;
        s_c2i[n] = 2.0f * cpi;
        s_dtr[n] = dtr;
        s_dti[n] = dti;
        float e64 = expf(64.0f * dtr);
        g_wS[(h * NST + n) * 2 + 0] = e64 * cosf(64.0f * dti);
        g_wS[(h * NST + n) * 2 + 1] = e64 * sinf(64.0f * dti);
    }
    __syncthreads();

    float kt = 0.0f;
    for (int n = 0; n < NST; n++) {
        float dtr = s_dtr[n], dti = s_dti[n];
        float c2r = s_c2r[n], c2i = s_c2i[n];
        float p = (float)(63 - t);
        float ep = expf(p * dtr);
        g_V[((long)h * CH + t) * CH + 2 * n]     = ep * cosf(p * dti);
        g_V[((long)h * CH + t) * CH + 2 * n + 1] = ep * sinf(p * dti);
        float pt = (float)t;
        float et = expf(pt * dtr);
        float wr = et * cosf(pt * dti), wi = et * sinf(pt * dti);
        kt += c2r * wr - c2i * wi;
        float p1 = (float)(t + 1);
        float e1 = expf(p1 * dtr);
        float w1r = e1 * cosf(p1 * dti), w1i = e1 * sinf(p1 * dti);
        g_CM[((long)h * 128 + 64 + 2 * n) * CH + t]     = c2r * w1r - c2i * w1i;
        g_CM[((long)h * 128 + 64 + 2 * n + 1) * CH + t] = -(c2r * w1i + c2i * w1r);
    }
    s_k[t] = kt;
    __syncthreads();
    for (int j = 0; j < CH; j++) {
        g_CM[((long)h * 128 + j) * CH + t] = (j <= t) ? s_k[t - j] : 0.0f;
    }
}

// ---------------- stage A: chunk-local end states ----------------
__global__ void __launch_bounds__(256, 2) stageA_kernel()
{
    int bh = blockIdx.x;
    int h = bh & (HH - 1);
    __shared__ float U[CH][68];
    __shared__ float Vt[CH][68];
    int tid = threadIdx.x;
    int tx = tid & 15, ty = tid >> 4;
    const float* up = g_u + (long)bh * LL;
    const float* vp = g_V + (long)h * CH * CH;
#pragma unroll
    for (int r = 0; r < 4; r++) {
        int i = tid + 256 * r;
        int c = i >> 4, t4 = (i & 15) << 2;
        *(float4*)&U[c][t4] = *(const float4*)(up + c * 64 + t4);
        *(float4*)&Vt[c][t4] = *(const float4*)(vp + c * 64 + t4);
    }
    __syncthreads();

    float acc[4][4];
#pragma unroll
    for (int i = 0; i < 4; i++)
#pragma unroll
        for (int j = 0; j < 4; j++) acc[i][j] = 0.0f;

#pragma unroll 8
    for (int t = 0; t < 64; t++) {
        float a[4];
#pragma unroll
        for (int i = 0; i < 4; i++) a[i] = U[ty * 4 + i][t];
        float4 b4 = *(const float4*)&Vt[t][tx * 4];
        float b[4] = {b4.x, b4.y, b4.z, b4.w};
#pragma unroll
        for (int i = 0; i < 4; i++)
#pragma unroll
            for (int j = 0; j < 4; j++)
                acc[i][j] = fmaf(a[i], b[j], acc[i][j]);
    }

    float* ep = g_E + (long)bh * LL;
#pragma unroll
    for (int i = 0; i < 4; i++) {
        float4 v = make_float4(acc[i][0], acc[i][1], acc[i][2], acc[i][3]);
        *(float4*)(ep + (ty * 4 + i) * 64 + tx * 4) = v;
    }
}

// ---------------- stage B: cross-chunk scan ----------------
__global__ void scan_kernel()
{
    int gid = blockIdx.x * blockDim.x + threadIdx.x;
    int bh = gid >> 5;
    int n = gid & 31;
    int h = bh & (HH - 1);
    float2* E2 = (float2*)g_E + (long)bh * (LL / 2);
    float wr = g_wS[(h * NST + n) * 2 + 0];
    float wi = g_wS[(h * NST + n) * 2 + 1];
    float sr = 0.0f, si = 0.0f;
    for (int c = 0; c < NC; c++) {
        float2 e = E2[c * 32 + n];
        E2[c * 32 + n] = make_float2(sr, si);
        float nsr = wr * sr - wi * si + e.x;
        si = wr * si + wi * sr + e.y;
        sr = nsr;
    }
}

// ---------------- stage C: Y = [u_chunk | P] * CM^T, + Dskip*u, gelu, +u ----------------
__global__ void __launch_bounds__(256, 1) stageC_kernel(const float* __restrict__ Dskip)
{
    int bh = blockIdx.x;
    int h = bh & (HH - 1);
    __shared__ float In[CH][132];
    __shared__ float CMs[16][68];
    int tid = threadIdx.x;
    int tx = tid & 15, ty = tid >> 4;
    const float* up = g_u + (long)bh * LL;
    const float* pp = g_E + (long)bh * LL;
#pragma unroll
    for (int r = 0; r < 4; r++) {
        int i = tid + 256 * r;
        int c = i >> 4, k4 = (i & 15) << 2;
        *(float4*)&In[c][k4] = *(const float4*)(up + c * 64 + k4);
        *(float4*)&In[c][64 + k4] = *(const float4*)(pp + c * 64 + k4);
    }

    float acc[4][4];
#pragma unroll
    for (int i = 0; i < 4; i++)
#pragma unroll
        for (int j = 0; j < 4; j++) acc[i][j] = 0.0f;

    const float* cmp = g_CM + (long)h * 128 * CH;
    for (int k0 = 0; k0 < 128; k0 += 16) {
        __syncthreads();
        {
            int kk = tid >> 4, t4 = (tid & 15) << 2;
            *(float4*)&CMs[kk][t4] = *(const float4*)(cmp + (k0 + kk) * 64 + t4);
        }
        __syncthreads();
#pragma unroll
        for (int kk = 0; kk < 16; kk++) {
            float a[4];
#pragma unroll
            for (int i = 0; i < 4; i++) a[i] = In[ty * 4 + i][k0 + kk];
            float4 b4 = *(const float4*)&CMs[kk][tx * 4];
            float b[4] = {b4.x, b4.y, b4.z, b4.w};
#pragma unroll
            for (int i = 0; i < 4; i++)
#pragma unroll
                for (int j = 0; j < 4; j++)
                    acc[i][j] = fmaf(a[i], b[j], acc[i][j]);
        }
    }

    float dsk = Dskip[h];
    float* hp = g_hres + (long)bh * LL;
#pragma unroll
    for (int i = 0; i < 4; i++) {
        int c = ty * 4 + i;
        float vv[4];
#pragma unroll
        for (int j = 0; j < 4; j++) {
            int t = tx * 4 + j;
            float uval = In[c][t];
            float y = acc[i][j] + dsk * uval;
            y = gelu_f(y);
            vv[j] = y + uval;
        }
        float4 o = make_float4(vv[0], vv[1], vv[2], vv[3]);
        *(float4*)(hp + c * 64 + tx * 4) = o;
    }
}

// ---------------- layernorm + transpose (B,H,L) -> (B,L,H) ----------------
__global__ void __launch_bounds__(256, 1) layernorm_kernel(const float* __restrict__ ln_g,
                                                           const float* __restrict__ ln_b)
{
    int b = blockIdx.y;
    int l0 = blockIdx.x * 32;
    __shared__ float tile[256][33];
    int tid = threadIdx.x;
    int w = tid >> 5, lane = tid & 31;
    const float* hp = g_hres + (long)b * HH * LL;
    for (int hh = w; hh < 256; hh += 8) {
        tile[hh][lane] = hp[(long)hh * LL + l0 + lane];
    }
    __syncthreads();
    float* op = g_tln + ((long)b * LL + l0) * HH;
#pragma unroll
    for (int q = 0; q < 4; q++) {
        int tok = w * 4 + q;
        float s = 0.0f, sq = 0.0f;
#pragma unroll
        for (int j = 0; j < 8; j++) {
            float v = tile[lane + 32 * j][tok];
            s += v;
            sq += v * v;
        }
#pragma unroll
        for (int o = 16; o > 0; o >>= 1) {
            s += __shfl_xor_sync(0xffffffffu, s, o);
            sq += __shfl_xor_sync(0xffffffffu, sq, o);
        }
        float mean = s * (1.0f / 256.0f);
        float var = sq * (1.0f / 256.0f) - mean * mean;
        float rstd = rsqrtf(var + 1e-5f);
#pragma unroll
        for (int j = 0; j < 8; j++) {
            int hh = lane + 32 * j;
            float v = (tile[hh][tok] - mean) * rstd * ln_g[hh] + ln_b[hh];
            op[(long)tok * HH + hh] = v;
        }
    }
}

// ---------------- launcher ----------------
extern "C" void kernel_launch(void* const* d_in, const int* in_sizes, int n_in,
                              void* d_out, int out_size)
{
    const float* x          = (const float*)d_in[0];
    const float* enc_w      = (const float*)d_in[1];
    const float* enc_b      = (const float*)d_in[2];
    const float* log_dt     = (const float*)d_in[3];
    const float* log_A_real = (const float*)d_in[4];
    const float* A_imag     = (const float*)d_in[5];
    const float* B_re       = (const float*)d_in[6];
    const float* B_im       = (const float*)d_in[7];
    const float* C_re       = (const float*)d_in[8];
    const float* C_im       = (const float*)d_in[9];
    const float* Dskip      = (const float*)d_in[10];
    const float* ln_g       = (const float*)d_in[11];
    const float* ln_b       = (const float*)d_in[12];
    const float* dec1_w     = (const float*)d_in[13];
    const float* dec1_b     = (const float*)d_in[14];
    const float* dec2_w     = (const float*)d_in[15];
    const float* dec2_b     = (const float*)d_in[16];
    float* out = (float*)d_out;

    void *pu = 0, *ptln = 0, *pz = 0;
    cudaGetSymbolAddress(&pu, g_u);
    cudaGetSymbolAddress(&ptln, g_tln);
    cudaGetSymbolAddress(&pz, g_z);

    // 1. per-head S4 matrices
    precompute_kernel<<<HH, 64>>>(log_dt, log_A_real, A_imag, B_re, B_im, C_re, C_im);

    // 2. encoder: (65536 x 256) = x(65536x100) * enc_w(256x100)^T, transposed store -> g_u (B,H,L)
    gemm_mma<false, true, true, false><<<dim3(HH / 128, (BB * LL) / 128), 256>>>(
        x, enc_w, enc_b, (float*)pu,
        BB * LL, HH, DIN, DIN, DIN, 0);

    // 3. chunk states
    stageA_kernel<<<BB * HH, 256>>>();

    // 4. cross-chunk scan
    scan_kernel<<<(BB * HH * NST) / 256, 256>>>();

    // 5. output stage + Dskip + gelu + residual
    stageC_kernel<<<BB * HH, 256>>>(Dskip);

    // 6. layernorm + transpose
    layernorm_kernel<<<dim3(LL / 32, BB), 256>>>(ln_g, ln_b);

    // 7. decoder MLP on tensor cores
    gemm_mma<true, false, false, false><<<dim3(DMID / 128, (BB * LL) / 128), 256>>>(
        (const float*)ptln, dec1_w, dec1_b, (float*)pz,
        BB * LL, DMID, HH, HH, HH, DMID);

    gemm_mma<false, false, false, true><<<dim3(1, (BB * LL) / 128), 256>>>(
        (const float*)pz, dec2_w, dec2_b, out,
        BB * LL, DOUTP, DMID, DMID, DMID, DOUTP);
}